// round 9
// baseline (speedup 1.0000x reference)
#include <cuda_runtime.h>
#include <cstdint>

#define NV 10000
#define NR 8
#define NC 64
#define NU 64
#define ROWS 128
#define NTHREADS 256

// ---- smem layout (bytes) ----
#define A_BUF  32768                 // 128 rows * 256B, swizzled stride-64
#define BT_BUF 8192                  // 1024 uint2: paired tf32 B, k 0..31
#define B2_BUF 8192                  // raw fp32 B, k 32..63 (32 rows * 256B)
#define OFF_A  0
#define OFF_BT (2*A_BUF)             // 65536
#define OFF_B2 (OFF_BT + 2*BT_BUF)   // 81920
#define SMEM_BYTES (OFF_B2 + 2*B2_BUF)   // 98304 -> 2 CTA/SM

__device__ __align__(16) float g_zero[64] = {};

// ---------------- helpers ----------------
__device__ __forceinline__ unsigned cvta_smem(const void* p) {
    unsigned r;
    asm("{ .reg .u64 t; cvta.to.shared.u64 t, %1; cvt.u32.u64 %0, t; }"
        : "=r"(r) : "l"(p));
    return r;
}
__device__ __forceinline__ void cpasync16(unsigned dst, const void* src) {
    asm volatile("cp.async.cg.shared.global [%0], [%1], 16;" :: "r"(dst), "l"(src));
}
#define CP_COMMIT() asm volatile("cp.async.commit_group;" ::: "memory")
#define CP_WAIT(n)  asm volatile("cp.async.wait_group %0;" :: "n"(n) : "memory")

__device__ __forceinline__ unsigned cvt_tf32(float f) {
    unsigned t;
    asm("cvt.rna.tf32.f32 %0, %1;" : "=r"(t) : "f"(f));
    return t;
}
__device__ __forceinline__ void ldsm_x4(unsigned addr, unsigned& r0, unsigned& r1,
                                        unsigned& r2, unsigned& r3) {
    asm volatile("ldmatrix.sync.aligned.m8n8.x4.shared.b16 {%0,%1,%2,%3}, [%4];"
                 : "=r"(r0), "=r"(r1), "=r"(r2), "=r"(r3) : "r"(addr));
}
__device__ __forceinline__ void mma_tf32(float& d0, float& d1, float& d2, float& d3,
                                         unsigned a0, unsigned a1, unsigned a2, unsigned a3,
                                         unsigned b0, unsigned b1) {
    asm volatile("mma.sync.aligned.m16n8k8.row.col.f32.tf32.tf32.f32 "
                 "{%0,%1,%2,%3}, {%4,%5,%6,%7}, {%8,%9}, {%0,%1,%2,%3};"
                 : "+f"(d0), "+f"(d1), "+f"(d2), "+f"(d3)
                 : "r"(a0), "r"(a1), "r"(a2), "r"(a3), "r"(b0), "r"(b1));
}
__device__ __forceinline__ unsigned long long fma2(unsigned long long a,
                                                   unsigned long long b,
                                                   unsigned long long c) {
    unsigned long long d;
    asm("fma.rn.f32x2 %0, %1, %2, %3;" : "=l"(d) : "l"(a), "l"(b), "l"(c));
    return d;
}
__device__ __forceinline__ unsigned long long bcast2(float x) {
    unsigned long long d;
    asm("mov.b64 %0, {%1, %1};" : "=l"(d) : "f"(x));
    return d;
}
__device__ __forceinline__ float2 unpack2(unsigned long long v) {
    float2 f;
    asm("mov.b64 {%0, %1}, %2;" : "=f"(f.x), "=f"(f.y) : "l"(v));
    return f;
}

__global__ void __launch_bounds__(NTHREADS, 2)
graphconv_hyb(const float* __restrict__ nodes,
              const int*   __restrict__ mapping,
              const float* __restrict__ kern,
              const float* __restrict__ bias,
              float*       __restrict__ out)
{
    extern __shared__ char smem[];
    const unsigned smem_u = cvta_smem(smem);

    const int tid  = threadIdx.x;
    const int row0 = blockIdx.x * ROWS;
    const int wid  = tid >> 5;
    const int l    = tid & 31;
    const int mg   = wid & 3;            // m-group: rows mg*32..+31
    const int ng   = wid >> 2;           // n-group: u ng*32..+31

    // gather roles: 2 lanes per row
    const int gm   = tid >> 1;           // local row 0..127
    const int gl   = tid & 1;
    const int grow = row0 + gm;
    const int bV   = (grow / NV) * NV;

    // lane-constant swizzle terms
    const int rx_t = l & 7;              // row&7 for ldsm rows (mg*32+(l&15))
    const int rx_f = l >> 2;             // row&7 for FFMA2 rows (...+(l>>2))

    float d[2][4][4];
    unsigned long long e[2][4][2];
#pragma unroll
    for (int mt = 0; mt < 2; ++mt)
#pragma unroll
        for (int nt = 0; nt < 4; ++nt) {
#pragma unroll
            for (int q = 0; q < 4; ++q) d[mt][nt][q] = 0.f;
            e[mt][nt][0] = 0ULL; e[mt][nt][1] = 0ULL;
        }

    int m_cur = __ldg(mapping + (size_t)grow * NR);

    // prologue: region 0
    {
        const float* src = (m_cur >= 0) ? nodes + ((size_t)(bV + m_cur) << 6) : g_zero;
        unsigned dA = smem_u + OFF_A + (unsigned)(gm * 256);
#pragma unroll
        for (int j = 0; j < 8; ++j) {
            const int jj = gl * 8 + j;
            cpasync16(dA + (unsigned)(((jj ^ (gm & 7)) << 4)), src + jj * 4);
        }
        // B2: 32 rows x 16 chunks = 512 chunks, 2 per thread
#pragma unroll
        for (int i = 0; i < 2; ++i) {
            const int c = tid + i * NTHREADS;    // 0..511
            const int k = c >> 4, ch = c & 15;
            cpasync16(smem_u + OFF_B2 + (unsigned)(k * 256 + ch * 16),
                      kern + (32 + k) * NU + ch * 4);
        }
        CP_COMMIT();
        uint2* Bn = (uint2*)(smem + OFF_BT);
#pragma unroll
        for (int i = 0; i < 4; ++i) {
            const int j  = tid + i * NTHREADS;   // 0..1023
            const int ks = j >> 8, kk = j & 3, u = (j >> 2) & 63;
            const int k0 = ks * 8 + kk;
            uint2 t;
            t.x = cvt_tf32(__ldg(kern + k0 * NU + u));
            t.y = cvt_tf32(__ldg(kern + (k0 + 4) * NU + u));
            Bn[j] = t;
        }
    }
    int m_nxt = __ldg(mapping + (size_t)grow * NR + 1);

#pragma unroll 1
    for (int r = 0; r < NR; ++r) {
        const int buf = r & 1;

        // ---- stage region r+1 ----
        if (r < NR - 1) {
            const int nb = buf ^ 1;
            const float* kg = kern + (size_t)(r + 1) * (NC * NU);
            const float* src = (m_nxt >= 0) ? nodes + ((size_t)(bV + m_nxt) << 6) : g_zero;
            unsigned dA = smem_u + OFF_A + (unsigned)(nb * A_BUF + gm * 256);
#pragma unroll
            for (int j = 0; j < 8; ++j) {
                const int jj = gl * 8 + j;
                cpasync16(dA + (unsigned)((jj ^ (gm & 7)) << 4), src + jj * 4);
            }
#pragma unroll
            for (int i = 0; i < 2; ++i) {
                const int c = tid + i * NTHREADS;
                const int k = c >> 4, ch = c & 15;
                cpasync16(smem_u + OFF_B2 + (unsigned)(nb * B2_BUF + k * 256 + ch * 16),
                          kg + (32 + k) * NU + ch * 4);
            }
            CP_COMMIT();
            uint2* Bn = (uint2*)(smem + OFF_BT + nb * BT_BUF);
#pragma unroll
            for (int i = 0; i < 4; ++i) {
                const int j  = tid + i * NTHREADS;
                const int ks = j >> 8, kk = j & 3, u = (j >> 2) & 63;
                const int k0 = ks * 8 + kk;
                uint2 t;
                t.x = cvt_tf32(__ldg(kg + k0 * NU + u));
                t.y = cvt_tf32(__ldg(kg + (k0 + 4) * NU + u));
                Bn[j] = t;
            }
            if (r < NR - 2) m_nxt = __ldg(mapping + (size_t)grow * NR + r + 2);
        }

        if (r < NR - 1) { CP_WAIT(1); } else { CP_WAIT(0); }
        __syncthreads();

        const unsigned abase = smem_u + OFF_A + (unsigned)(buf * A_BUF);
        const uint2*  Bt = (const uint2*)(smem + OFF_BT + buf * BT_BUF);
        const float2* B2 = (const float2*)(smem + OFF_B2 + buf * B2_BUF);

        // per-lane fixed addr parts
        const unsigned a_ld = abase + (unsigned)((mg * 32 + (l & 15)) * 256);
        const unsigned a_ff = abase + (unsigned)((mg * 32 + (l >> 2)) * 256);
        const int bt_l = ng * 128 + (l >> 2) * 4 + (l & 3);
        const int b2_l = ng * 16 + (l & 3);

#pragma unroll
        for (int ks = 0; ks < 4; ++ks) {
            // ---- tensor half: k = ks*8 .. ks*8+7 ----
            uint2 bfr[4];
#pragma unroll
            for (int nt = 0; nt < 4; ++nt) bfr[nt] = Bt[ks * 256 + bt_l + nt * 32];

            unsigned a[2][4];
#pragma unroll
            for (int mt = 0; mt < 2; ++mt) {
                unsigned addr = a_ld + (unsigned)(mt * 16 * 256)
                              + (unsigned)((((ks * 2 + (l >> 4)) ^ rx_t) << 4));
                ldsm_x4(addr, a[mt][0], a[mt][1], a[mt][2], a[mt][3]);
#pragma unroll
                for (int q = 0; q < 4; ++q)
                    a[mt][q] = cvt_tf32(__uint_as_float(a[mt][q]));
            }
#pragma unroll
            for (int mt = 0; mt < 2; ++mt)
#pragma unroll
                for (int nt = 0; nt < 4; ++nt)
                    mma_tf32(d[mt][nt][0], d[mt][nt][1], d[mt][nt][2], d[mt][nt][3],
                             a[mt][0], a[mt][1], a[mt][2], a[mt][3],
                             bfr[nt].x, bfr[nt].y);

            // ---- FFMA2 half: chunks qa = 8 + 2ks, 8 + 2ks + 1 (k 32..63) ----
#pragma unroll
            for (int q2 = 0; q2 < 2; ++q2) {
                const int q  = 2 * ks + q2;       // 0..7 -> k = 32 + 4q
                const int qa = 8 + q;
                float4 av[2][2];
#pragma unroll
                for (int mt = 0; mt < 2; ++mt)
#pragma unroll
                    for (int h = 0; h < 2; ++h) {
                        unsigned addr = a_ff + (unsigned)((mt * 16 + h * 8) * 256)
                                      + (unsigned)(((qa ^ rx_f) << 4));
                        av[mt][h] = *(const float4*)(smem + (addr - smem_u));
                    }
#pragma unroll
                for (int kk = 0; kk < 4; ++kk) {
                    unsigned long long b2v[4];
#pragma unroll
                    for (int nt = 0; nt < 4; ++nt)
                        b2v[nt] = *(const unsigned long long*)
                                  (B2 + (q * 4 + kk) * 32 + b2_l + nt * 4);
                    const float* avf[2][2] = {
                        {(const float*)&av[0][0], (const float*)&av[0][1]},
                        {(const float*)&av[1][0], (const float*)&av[1][1]}};
#pragma unroll
                    for (int mt = 0; mt < 2; ++mt)
#pragma unroll
                        for (int h = 0; h < 2; ++h) {
                            unsigned long long ax = bcast2(avf[mt][h][kk]);
#pragma unroll
                            for (int nt = 0; nt < 4; ++nt)
                                e[mt][nt][h] = fma2(ax, b2v[nt], e[mt][nt][h]);
                        }
                }
            }
        }
        __syncthreads();   // all warps done reading buf before refill
    }

    // ---- epilogue: merge tensor + FFMA2 accs, bias + relu, STG.64 ----
#pragma unroll
    for (int nt = 0; nt < 4; ++nt) {
        const int u0 = ng * 32 + nt * 8 + 2 * (l & 3);
        float2 bv = *(const float2*)(bias + u0);
#pragma unroll
        for (int mt = 0; mt < 2; ++mt) {
            const int rA = row0 + mg * 32 + mt * 16 + (l >> 2);
            float2 e0 = unpack2(e[mt][nt][0]);
            float2 e1 = unpack2(e[mt][nt][1]);
            float2 o0, o1;
            o0.x = fmaxf(d[mt][nt][0] + e0.x + bv.x, 0.f);
            o0.y = fmaxf(d[mt][nt][1] + e0.y + bv.y, 0.f);
            o1.x = fmaxf(d[mt][nt][2] + e1.x + bv.x, 0.f);
            o1.y = fmaxf(d[mt][nt][3] + e1.y + bv.y, 0.f);
            *(float2*)(out + (size_t)rA * NU + u0)       = o0;
            *(float2*)(out + (size_t)(rA + 8) * NU + u0) = o1;
        }
    }
}

extern "C" void kernel_launch(void* const* d_in, const int* in_sizes, int n_in,
                              void* d_out, int out_size) {
    (void)in_sizes; (void)n_in; (void)out_size;
    const float* nodes   = (const float*)d_in[0];
    const int*   mapping = (const int*)d_in[1];
    const float* kern    = (const float*)d_in[2];
    const float* bias    = (const float*)d_in[3];
    float*       out     = (float*)d_out;

    cudaFuncSetAttribute(graphconv_hyb,
                         cudaFuncAttributeMaxDynamicSharedMemorySize, SMEM_BYTES);

    int grid = (16 * NV) / ROWS;   // 1250
    graphconv_hyb<<<grid, NTHREADS, SMEM_BYTES>>>(nodes, mapping, kern, bias, out);
}